// round 4
// baseline (speedup 1.0000x reference)
#include <cuda_runtime.h>

#define NN 100000
#define EE 1600000
#define BB 64
#define BNEPS 1e-5f

// ---------------- scratch ----------------
__device__ __align__(16) float g_P[(size_t)NN * 32];   // pre-scaled scatter source
__device__ __align__(16) float g_A[(size_t)NN * 32];   // aggregation result
__device__ __align__(16) float g_Y[(size_t)NN * 64];   // layer output
__device__ int g_degi[NN];
__device__ int g_rowptr[NN + 1];
__device__ int g_cursor[NN];
__device__ int g_src[EE];
__device__ int g_batch[NN];
__device__ float g_dis[NN];
__device__ float g_stats[128];
__device__ __align__(16) float g_pool[BB * 64];
__device__ float g_cnt[BB];
__device__ int g_is64_e;
__device__ int g_is64_b;

// ---------------- dtype detection ----------------
__global__ void detect_dtype_kernel(const void* ei, const void* batch) {
    if (threadIdx.x != 0 || blockIdx.x != 0) return;
    const long long* p = (const long long*)ei;
    int ok = 1;
    for (int i = 0; i < 64; i++) {
        long long v = p[i];
        if (v < 0 || v >= NN) ok = 0;
    }
    g_is64_e = ok;
    const long long* q = (const long long*)batch;
    int okb = 1;
    for (int i = 0; i < 32; i++) {
        long long v = q[NN / 4 + i];
        if (v < 0 || v >= BB) okb = 0;
    }
    g_is64_b = okb;
}

__global__ void zero_deg_kernel() {
    int i = blockIdx.x * blockDim.x + threadIdx.x;
    if (i < NN) g_degi[i] = 0;
}

__global__ void hist_kernel(const void* ei) {
    int e = blockIdx.x * blockDim.x + threadIdx.x;
    if (e >= EE) return;
    int c = g_is64_e ? (int)((const long long*)ei)[EE + e] : ((const int*)ei)[EE + e];
    atomicAdd(&g_degi[c], 1);
}

// single-block exclusive scan over g_degi -> g_rowptr / g_cursor; also dis
__global__ void scan_kernel() {
    __shared__ int ssum[1024];
    int t = threadIdx.x;
    const int CH = (NN + 1023) / 1024;
    int base = t * CH;
    int s = 0;
    for (int i = 0; i < CH; i++) {
        int idx = base + i;
        if (idx < NN) s += g_degi[idx];
    }
    ssum[t] = s;
    __syncthreads();
    for (int off = 1; off < 1024; off <<= 1) {
        int v = (t >= off) ? ssum[t - off] : 0;
        __syncthreads();
        ssum[t] += v;
        __syncthreads();
    }
    int run = (t == 0) ? 0 : ssum[t - 1];
    for (int i = 0; i < CH; i++) {
        int idx = base + i;
        if (idx < NN) {
            g_rowptr[idx] = run;
            g_cursor[idx] = run;
            run += g_degi[idx];
            g_dis[idx] = rsqrtf((float)(g_degi[idx] + 1));
        }
    }
    if (t == 1023) g_rowptr[NN] = run;
}

__global__ void fill_kernel(const void* ei) {
    int e = blockIdx.x * blockDim.x + threadIdx.x;
    if (e >= EE) return;
    int r, c;
    if (g_is64_e) {
        const long long* p = (const long long*)ei;
        r = (int)p[e]; c = (int)p[EE + e];
    } else {
        const int* p = (const int*)ei;
        r = p[e]; c = p[EE + e];
    }
    int pos = atomicAdd(&g_cursor[c], 1);
    g_src[pos] = r;
}

__global__ void decode_batch_kernel(const void* batch) {
    int i = blockIdx.x * blockDim.x + threadIdx.x;
    if (i >= NN) return;
    g_batch[i] = g_is64_b ? (int)((const long long*)batch)[i]
                          : ((const int*)batch)[i];
}

// ---------------- layer 1 prep: P = [x*dis, 0-pad] ----------------
__global__ void prep1_kernel(const float* __restrict__ x) {
    int i = blockIdx.x * blockDim.x + threadIdx.x;
    if (i >= NN) return;
    float d = g_dis[i];
    ((float4*)g_P)[i] = make_float4(x[3 * i] * d, x[3 * i + 1] * d, x[3 * i + 2] * d, 0.0f);
}

// ---------------- CSR gather: A[i] = P[i] + sum_{j in nbrs(i)} P[src[j]] ----------------
__global__ void gather_kernel(const float4* __restrict__ P4, float4* __restrict__ A4,
                              int q, int lq) {
    int idx = blockIdx.x * blockDim.x + threadIdx.x;
    int total = NN * q;
    if (idx >= total) return;
    int i = idx >> lq;
    int c = idx & (q - 1);
    float4 acc = P4[idx];               // self-loop term
    int s = g_rowptr[i], e = g_rowptr[i + 1];
    for (int j = s; j < e; j++) {
        int r = g_src[j];
        float4 v = P4[((size_t)r << lq) + c];
        acc.x += v.x; acc.y += v.y; acc.z += v.z; acc.w += v.w;
    }
    A4[idx] = acc;
}

__global__ void zero_stats_kernel() {
    int t = threadIdx.x;
    if (t < 128) g_stats[t] = 0.0f;
}

// ---------------- Y = (A @ W) * dis + b ; accumulate channel stats ----------------
__global__ void linear_stats_kernel(const float* __restrict__ A, const float* __restrict__ W,
                                    const float* __restrict__ bias, float* __restrict__ Y,
                                    int din, int astride, int dout, int ld) {
    extern __shared__ float Wsh[];
    for (int i = threadIdx.x; i < din * dout; i += blockDim.x) Wsh[i] = W[i];
    __syncthreads();
    __shared__ float sh[256];
    __shared__ float sh2[256];
    int t = threadIdx.x;
    int c = t & (dout - 1);
    int rpb = 256 >> ld;
    int rstart = blockIdx.x * rpb + (t >> ld);
    int rstride = gridDim.x * rpb;
    float bc = bias[c];
    float s = 0.0f, s2 = 0.0f;
    for (int i = rstart; i < NN; i += rstride) {
        const float* a = A + (size_t)i * astride;
        float dot = 0.0f;
        for (int k = 0; k < din; k++) dot += a[k] * Wsh[k * dout + c];
        float y = dot * g_dis[i] + bc;
        Y[(size_t)i * dout + c] = y;
        s += y; s2 += y * y;
    }
    sh[t] = s; sh2[t] = s2;
    __syncthreads();
    for (int off = 128; off >= dout; off >>= 1) {
        if (t < off) { sh[t] += sh[t + off]; sh2[t] += sh2[t + off]; }
        __syncthreads();
    }
    if (t < dout) {
        atomicAdd(&g_stats[c], sh[t]);
        atomicAdd(&g_stats[64 + c], sh2[t]);
    }
}

// ---------------- bn+relu; optionally emit next layer's P (=h*dis) ----------------
__global__ void bn_next_kernel(float* __restrict__ Y, const float* __restrict__ g,
                               const float* __restrict__ be, int dout, int ld,
                               float* __restrict__ Pout, int write_scaled) {
    size_t idx = (size_t)blockIdx.x * blockDim.x + threadIdx.x;
    size_t total = (size_t)NN * dout;
    if (idx >= total) return;
    int c = (int)(idx & (dout - 1));
    int i = (int)(idx >> ld);
    float mean = g_stats[c] * (1.0f / NN);
    float var  = g_stats[64 + c] * (1.0f / NN) - mean * mean;
    float inv  = rsqrtf(var + BNEPS);
    float a  = g[c] * inv;
    float shv = be[c] - mean * a;
    float h = fmaxf(Y[idx] * a + shv, 0.0f);
    if (write_scaled) Pout[idx] = h * g_dis[i];
    else Y[idx] = h;
}

// ---------------- pooling + FC ----------------
__global__ void zero_pool_kernel() {
    int t = blockIdx.x * blockDim.x + threadIdx.x;
    if (t < BB * 64) g_pool[t] = 0.0f;
    if (t < BB) g_cnt[t] = 0.0f;
}

__global__ void pool_kernel(const float4* __restrict__ H4) {
    int idx = blockIdx.x * blockDim.x + threadIdx.x;
    if (idx >= NN * 16) return;
    int i = idx >> 4;
    int c = idx & 15;
    int b = g_batch[i];
    float4 v = H4[(size_t)i * 16 + c];
    float* dst = g_pool + ((size_t)b * 16 + c) * 4;
    unsigned long long p = (unsigned long long)__cvta_generic_to_global(dst);
    asm volatile("red.global.add.v4.f32 [%0], {%1,%2,%3,%4};"
                 :: "l"(p), "f"(v.x), "f"(v.y), "f"(v.z), "f"(v.w) : "memory");
    if (c == 0) atomicAdd(&g_cnt[b], 1.0f);
}

__global__ void fc_kernel(const float* __restrict__ fcW, const float* __restrict__ fcb,
                          float* __restrict__ out) {
    int t = blockIdx.x * blockDim.x + threadIdx.x;
    if (t >= BB * 10) return;
    int b = t / 10;
    int k = t % 10;
    float cnt = fmaxf(g_cnt[b], 1.0f);
    float s = 0.0f;
    for (int j = 0; j < 64; j++) s += g_pool[b * 64 + j] * fcW[j * 10 + k];
    out[t] = s / cnt + fcb[k];
}

extern "C" void kernel_launch(void* const* d_in, const int* in_sizes, int n_in,
                              void* d_out, int out_size) {
    const float* x     = (const float*)d_in[0];
    const void*  ei    = d_in[1];
    const void*  batch = d_in[2];
    const float* W1 = (const float*)d_in[3];
    const float* b1 = (const float*)d_in[4];
    const float* g1 = (const float*)d_in[5];
    const float* be1 = (const float*)d_in[6];
    const float* W2 = (const float*)d_in[7];
    const float* b2 = (const float*)d_in[8];
    const float* g2 = (const float*)d_in[9];
    const float* be2 = (const float*)d_in[10];
    const float* W3 = (const float*)d_in[11];
    const float* b3 = (const float*)d_in[12];
    const float* g3 = (const float*)d_in[13];
    const float* be3 = (const float*)d_in[14];
    const float* fcW = (const float*)d_in[15];
    const float* fcb = (const float*)d_in[16];
    float* out = (float*)d_out;

    float *Pp, *Ap, *Yp;
    cudaGetSymbolAddress((void**)&Pp, g_P);
    cudaGetSymbolAddress((void**)&Ap, g_A);
    cudaGetSymbolAddress((void**)&Yp, g_Y);

    // ---- CSR build ----
    detect_dtype_kernel<<<1, 32>>>(ei, batch);
    zero_deg_kernel<<<(NN + 255) / 256, 256>>>();
    hist_kernel<<<(EE + 255) / 256, 256>>>(ei);
    scan_kernel<<<1, 1024>>>();
    fill_kernel<<<(EE + 255) / 256, 256>>>(ei);
    decode_batch_kernel<<<(NN + 255) / 256, 256>>>(batch);

    // ---- layer 1: gather 4 padded channels, then @W1 (3->16) ----
    prep1_kernel<<<(NN + 255) / 256, 256>>>(x);
    gather_kernel<<<(NN + 255) / 256, 256>>>((const float4*)Pp, (float4*)Ap, 1, 0);
    zero_stats_kernel<<<1, 128>>>();
    linear_stats_kernel<<<1024, 256, 3 * 16 * sizeof(float)>>>(Ap, W1, b1, Yp, 3, 4, 16, 4);
    bn_next_kernel<<<(NN * 16 + 255) / 256, 256>>>(Yp, g1, be1, 16, 4, Pp, 1);

    // ---- layer 2: gather 16 channels, then @W2 (16->32) ----
    gather_kernel<<<(NN * 4 + 255) / 256, 256>>>((const float4*)Pp, (float4*)Ap, 4, 2);
    zero_stats_kernel<<<1, 128>>>();
    linear_stats_kernel<<<1024, 256, 16 * 32 * sizeof(float)>>>(Ap, W2, b2, Yp, 16, 16, 32, 5);
    bn_next_kernel<<<(NN * 32 + 255) / 256, 256>>>(Yp, g2, be2, 32, 5, Pp, 1);

    // ---- layer 3: gather 32 channels, then @W3 (32->64) ----
    gather_kernel<<<(NN * 8 + 255) / 256, 256>>>((const float4*)Pp, (float4*)Ap, 8, 3);
    zero_stats_kernel<<<1, 128>>>();
    linear_stats_kernel<<<1024, 256, 32 * 64 * sizeof(float)>>>(Ap, W3, b3, Yp, 32, 32, 64, 6);
    bn_next_kernel<<<(NN * 64 + 255) / 256, 256>>>(Yp, g3, be3, 64, 6, Pp, 0);

    // ---- pooling + FC ----
    zero_pool_kernel<<<(BB * 64 + 255) / 256, 256>>>();
    pool_kernel<<<(NN * 16 + 255) / 256, 256>>>((const float4*)Yp);
    fc_kernel<<<(BB * 10 + 255) / 256, 256>>>(fcW, fcb, out);
}

// round 6
// speedup vs baseline: 1.1995x; 1.1995x over previous
#include <cuda_runtime.h>

#define NN 100000
#define EE 1600000
#define BB 64
#define BNEPS 1e-5f
#define NBLK ((NN + 1023) / 1024)

// ---------------- scratch ----------------
__device__ __align__(16) float g_P[(size_t)NN * 32];
__device__ __align__(16) float g_A[(size_t)NN * 32];
__device__ __align__(16) float g_Y[(size_t)NN * 64];
__device__ __align__(16) int g_degi[NN];
__device__ int g_rowptr[NN + 1];
__device__ int g_cursor[NN];
__device__ int g_src[EE];
__device__ int g_batch[NN];
__device__ float g_dis[NN];
__device__ float g_stats[128];      // [0:64) scale, [64:128) offset
__device__ float g_M[1056];         // M1[din] then M2[din*din]
__device__ int g_bsum[NBLK];
__device__ int g_boff[NBLK];
__device__ __align__(16) float g_pool[BB * 64];
__device__ float g_cnt[BB];
__device__ int g_is64_e;
__device__ int g_is64_b;

// ---------------- dtype detection ----------------
__global__ void detect_dtype_kernel(const void* ei, const void* batch) {
    if (threadIdx.x != 0 || blockIdx.x != 0) return;
    const long long* p = (const long long*)ei;
    int ok = 1;
    for (int i = 0; i < 64; i++) {
        long long v = p[i];
        if (v < 0 || v >= NN) ok = 0;
    }
    g_is64_e = ok;
    const long long* q = (const long long*)batch;
    int okb = 1;
    for (int i = 0; i < 32; i++) {
        long long v = q[NN / 4 + i];
        if (v < 0 || v >= BB) okb = 0;
    }
    g_is64_b = okb;
}

__global__ void hist_kernel(const void* ei) {
    int e = blockIdx.x * blockDim.x + threadIdx.x;
    if (e >= EE) return;
    int c = g_is64_e ? (int)((const long long*)ei)[EE + e] : ((const int*)ei)[EE + e];
    atomicAdd(&g_degi[c], 1);
}

// ---------------- fast 3-phase scan ----------------
__global__ void scan1_kernel() {           // grid NBLK, 256 thr: block partial sums
    __shared__ int s[256];
    int t = threadIdx.x;
    int base = blockIdx.x * 1024 + t * 4;
    int sum = 0;
    if (base + 3 < NN) {
        int4 d = *(const int4*)&g_degi[base];
        sum = d.x + d.y + d.z + d.w;
    } else {
        for (int u = 0; u < 4; u++) if (base + u < NN) sum += g_degi[base + u];
    }
    s[t] = sum;
    __syncthreads();
    for (int off = 128; off > 0; off >>= 1) {
        if (t < off) s[t] += s[t + off];
        __syncthreads();
    }
    if (t == 0) g_bsum[blockIdx.x] = s[0];
}

__global__ void scan2_kernel() {           // 1 block, 128 thr: scan NBLK sums
    __shared__ int s[128];
    int t = threadIdx.x;
    int v = (t < NBLK) ? g_bsum[t] : 0;
    s[t] = v;
    __syncthreads();
    for (int off = 1; off < 128; off <<= 1) {
        int u = (t >= off) ? s[t - off] : 0;
        __syncthreads();
        s[t] += u;
        __syncthreads();
    }
    if (t < NBLK) g_boff[t] = s[t] - v;    // exclusive
    if (t == 127) g_rowptr[NN] = s[127];
}

__global__ void scan3_kernel() {           // grid NBLK, 256 thr: write rowptr/cursor/dis
    __shared__ int s[256];
    int t = threadIdx.x;
    int base = blockIdx.x * 1024 + t * 4;
    int d0 = 0, d1 = 0, d2 = 0, d3 = 0;
    if (base + 3 < NN) {
        int4 d = *(const int4*)&g_degi[base];
        d0 = d.x; d1 = d.y; d2 = d.z; d3 = d.w;
    } else {
        if (base + 0 < NN) d0 = g_degi[base + 0];
        if (base + 1 < NN) d1 = g_degi[base + 1];
        if (base + 2 < NN) d2 = g_degi[base + 2];
        if (base + 3 < NN) d3 = g_degi[base + 3];
    }
    int tsum = d0 + d1 + d2 + d3;
    s[t] = tsum;
    __syncthreads();
    for (int off = 1; off < 256; off <<= 1) {
        int u = (t >= off) ? s[t - off] : 0;
        __syncthreads();
        s[t] += u;
        __syncthreads();
    }
    int off = g_boff[blockIdx.x] + s[t] - tsum;
    int pre[4] = {off, off + d0, off + d0 + d1, off + d0 + d1 + d2};
    int dd[4] = {d0, d1, d2, d3};
    for (int u = 0; u < 4; u++) {
        int idx = base + u;
        if (idx < NN) {
            g_rowptr[idx] = pre[u];
            g_cursor[idx] = pre[u];
            g_dis[idx] = rsqrtf((float)(dd[u] + 1));
        }
    }
}

__global__ void fill_kernel(const void* ei) {
    int e = blockIdx.x * blockDim.x + threadIdx.x;
    if (e >= EE) return;
    int r, c;
    if (g_is64_e) {
        const long long* p = (const long long*)ei;
        r = (int)p[e]; c = (int)p[EE + e];
    } else {
        const int* p = (const int*)ei;
        r = p[e]; c = p[EE + e];
    }
    int pos = atomicAdd(&g_cursor[c], 1);
    g_src[pos] = r;
}

__global__ void decode_batch_kernel(const void* batch) {
    int i = blockIdx.x * blockDim.x + threadIdx.x;
    if (i >= NN) return;
    g_batch[i] = g_is64_b ? (int)((const long long*)batch)[i]
                          : ((const int*)batch)[i];
}

// ---------------- layer 1 prep: P = [x*dis, 0-pad] ----------------
__global__ void prep1_kernel(const float* __restrict__ x) {
    int i = blockIdx.x * blockDim.x + threadIdx.x;
    if (i >= NN) return;
    float d = g_dis[i];
    ((float4*)g_P)[i] = make_float4(x[3 * i] * d, x[3 * i + 1] * d, x[3 * i + 2] * d, 0.0f);
}

// ---------------- CSR gather: A[i] = P[i] + sum_{j} P[src[j]] ----------------
__global__ void gather_kernel(const float4* __restrict__ P4, float4* __restrict__ A4,
                              int q, int lq) {
    int idx = blockIdx.x * blockDim.x + threadIdx.x;
    int total = NN * q;
    if (idx >= total) return;
    int i = idx >> lq;
    int c = idx & (q - 1);
    float4 acc = P4[idx];               // self-loop term
    int s = g_rowptr[i], e = g_rowptr[i + 1];
    for (int j = s; j < e; j++) {
        int r = g_src[j];
        float4 v = P4[((size_t)r << lq) + c];
        acc.x += v.x; acc.y += v.y; acc.z += v.z; acc.w += v.w;
    }
    A4[idx] = acc;
}

// ---------------- moments: M1 = sum dis*A, M2 = sum dis^2 * A A^T ----------------
#define MTR 8
__global__ void moments_kernel(const float* __restrict__ A, int din, int astride) {
    __shared__ float tile[MTR * 32];
    __shared__ float dsh[MTR];
    int t = threadIdx.x;
    int nitems = din * din + din;
    float acc[5];
#pragma unroll
    for (int u = 0; u < 5; u++) acc[u] = 0.0f;
    for (int row0 = blockIdx.x * MTR; row0 < NN; row0 += gridDim.x * MTR) {
        int nr = min(MTR, NN - row0);
        for (int u = t; u < nr * astride; u += 256)
            tile[u] = A[(size_t)row0 * astride + u];
        if (t < nr) dsh[t] = g_dis[row0 + t];
        __syncthreads();
        int ui = 0;
        for (int p = t; p < nitems; p += 256, ui++) {
            float a = 0.0f;
            if (p < din) {
                for (int r = 0; r < nr; r++) a += dsh[r] * tile[r * astride + p];
            } else {
                int pj = (p - din) / din, pk = (p - din) % din;
                for (int r = 0; r < nr; r++) {
                    float dd = dsh[r];
                    a += dd * dd * tile[r * astride + pj] * tile[r * astride + pk];
                }
            }
            acc[ui] += a;
        }
        __syncthreads();
    }
    int ui = 0;
    for (int p = t; p < nitems; p += 256, ui++)
        atomicAdd(&g_M[p], acc[ui]);
}

// ---------------- solve BN affine from moments ----------------
__global__ void solve_kernel(const float* __restrict__ W, const float* __restrict__ bias,
                             const float* __restrict__ g, const float* __restrict__ be,
                             int din, int dout) {
    int c = threadIdx.x;
    if (c >= dout) return;
    float m1w = 0.0f;
    for (int k = 0; k < din; k++) m1w += g_M[k] * W[k * dout + c];
    float q = 0.0f;
    for (int j = 0; j < din; j++) {
        float wj = W[j * dout + c];
        for (int k = 0; k < din; k++) q += wj * g_M[din + j * din + k] * W[k * dout + c];
    }
    float bc = bias[c];
    const float inv_n = 1.0f / NN;
    float mu  = m1w * inv_n + bc;
    float ex2 = q * inv_n + 2.0f * bc * m1w * inv_n + bc * bc;
    float var = ex2 - mu * mu;
    float scale = g[c] * rsqrtf(var + BNEPS);
    float off = (bc - mu) * scale + be[c];
    g_stats[c] = scale;
    g_stats[64 + c] = off;
}

// ---------------- fused: h = relu(bn(dis*(A@W)+b)); P = h*dis or Y = h ----------------
__global__ void fused_out_kernel(const float* __restrict__ A, const float* __restrict__ W,
                                 float* __restrict__ Pout, float* __restrict__ Yout,
                                 int din, int astride, int dout, int ld, int write_scaled) {
    extern __shared__ float Wsh[];
    for (int i = threadIdx.x; i < din * dout; i += blockDim.x) Wsh[i] = W[i];
    __syncthreads();
    int t = threadIdx.x;
    int c = t & (dout - 1);
    float scale = g_stats[c];
    float off = g_stats[64 + c];
    int rpb = 256 >> ld;
    int rstart = blockIdx.x * rpb + (t >> ld);
    int rstride = gridDim.x * rpb;
    for (int i = rstart; i < NN; i += rstride) {
        const float* a = A + (size_t)i * astride;
        float dot = 0.0f;
        for (int k = 0; k < din; k++) dot += a[k] * Wsh[k * dout + c];
        float d = g_dis[i];
        float h = fmaxf(d * dot * scale + off, 0.0f);
        size_t oidx = (size_t)i * dout + c;
        if (write_scaled) Pout[oidx] = h * d;
        else Yout[oidx] = h;
    }
}

// ---------------- pooling + FC ----------------
__global__ void pool_kernel(const float4* __restrict__ H4) {
    int idx = blockIdx.x * blockDim.x + threadIdx.x;
    if (idx >= NN * 16) return;
    int i = idx >> 4;
    int c = idx & 15;
    int b = g_batch[i];
    float4 v = H4[(size_t)i * 16 + c];
    float* dst = g_pool + ((size_t)b * 16 + c) * 4;
    unsigned long long p = (unsigned long long)__cvta_generic_to_global(dst);
    asm volatile("red.global.add.v4.f32 [%0], {%1,%2,%3,%4};"
                 :: "l"(p), "f"(v.x), "f"(v.y), "f"(v.z), "f"(v.w) : "memory");
    if (c == 0) atomicAdd(&g_cnt[b], 1.0f);
}

__global__ void fc_kernel(const float* __restrict__ fcW, const float* __restrict__ fcb,
                          float* __restrict__ out) {
    int t = blockIdx.x * blockDim.x + threadIdx.x;
    if (t >= BB * 10) return;
    int b = t / 10;
    int k = t % 10;
    float cnt = fmaxf(g_cnt[b], 1.0f);
    float s = 0.0f;
    for (int j = 0; j < 64; j++) s += g_pool[b * 64 + j] * fcW[j * 10 + k];
    out[t] = s / cnt + fcb[k];
}

extern "C" void kernel_launch(void* const* d_in, const int* in_sizes, int n_in,
                              void* d_out, int out_size) {
    const float* x     = (const float*)d_in[0];
    const void*  ei    = d_in[1];
    const void*  batch = d_in[2];
    const float* W1 = (const float*)d_in[3];
    const float* b1 = (const float*)d_in[4];
    const float* g1 = (const float*)d_in[5];
    const float* be1 = (const float*)d_in[6];
    const float* W2 = (const float*)d_in[7];
    const float* b2 = (const float*)d_in[8];
    const float* g2 = (const float*)d_in[9];
    const float* be2 = (const float*)d_in[10];
    const float* W3 = (const float*)d_in[11];
    const float* b3 = (const float*)d_in[12];
    const float* g3 = (const float*)d_in[13];
    const float* be3 = (const float*)d_in[14];
    const float* fcW = (const float*)d_in[15];
    const float* fcb = (const float*)d_in[16];
    float* out = (float*)d_out;

    float *Pp, *Ap, *Yp, *Mp, *poolp, *cntp;
    int* degp;
    cudaGetSymbolAddress((void**)&Pp, g_P);
    cudaGetSymbolAddress((void**)&Ap, g_A);
    cudaGetSymbolAddress((void**)&Yp, g_Y);
    cudaGetSymbolAddress((void**)&Mp, g_M);
    cudaGetSymbolAddress((void**)&poolp, g_pool);
    cudaGetSymbolAddress((void**)&cntp, g_cnt);
    cudaGetSymbolAddress((void**)&degp, g_degi);

    // ---- CSR build ----
    detect_dtype_kernel<<<1, 32>>>(ei, batch);
    cudaMemsetAsync(degp, 0, NN * sizeof(int));
    hist_kernel<<<(EE + 255) / 256, 256>>>(ei);
    scan1_kernel<<<NBLK, 256>>>();
    scan2_kernel<<<1, 128>>>();
    scan3_kernel<<<NBLK, 256>>>();
    fill_kernel<<<(EE + 255) / 256, 256>>>(ei);
    decode_batch_kernel<<<(NN + 255) / 256, 256>>>(batch);

    // ---- layer 1 (3->16) ----
    prep1_kernel<<<(NN + 255) / 256, 256>>>(x);
    gather_kernel<<<(NN + 255) / 256, 256>>>((const float4*)Pp, (float4*)Ap, 1, 0);
    cudaMemsetAsync(Mp, 0, (3 * 3 + 3) * sizeof(float));
    moments_kernel<<<512, 256>>>(Ap, 3, 4);
    solve_kernel<<<1, 64>>>(W1, b1, g1, be1, 3, 16);
    fused_out_kernel<<<1024, 256, 3 * 16 * sizeof(float)>>>(Ap, W1, Pp, Yp, 3, 4, 16, 4, 1);

    // ---- layer 2 (16->32) ----
    gather_kernel<<<(NN * 4 + 255) / 256, 256>>>((const float4*)Pp, (float4*)Ap, 4, 2);
    cudaMemsetAsync(Mp, 0, (16 * 16 + 16) * sizeof(float));
    moments_kernel<<<512, 256>>>(Ap, 16, 16);
    solve_kernel<<<1, 64>>>(W2, b2, g2, be2, 16, 32);
    fused_out_kernel<<<1024, 256, 16 * 32 * sizeof(float)>>>(Ap, W2, Pp, Yp, 16, 16, 32, 5, 1);

    // ---- layer 3 (32->64) ----
    gather_kernel<<<(NN * 8 + 255) / 256, 256>>>((const float4*)Pp, (float4*)Ap, 8, 3);
    cudaMemsetAsync(Mp, 0, (32 * 32 + 32) * sizeof(float));
    moments_kernel<<<512, 256>>>(Ap, 32, 32);
    solve_kernel<<<1, 64>>>(W3, b3, g3, be3, 32, 64);
    fused_out_kernel<<<1024, 256, 32 * 64 * sizeof(float)>>>(Ap, W3, Pp, Yp, 32, 32, 64, 6, 0);

    // ---- pooling + FC ----
    cudaMemsetAsync(poolp, 0, BB * 64 * sizeof(float));
    cudaMemsetAsync(cntp, 0, BB * sizeof(float));
    pool_kernel<<<(NN * 16 + 255) / 256, 256>>>((const float4*)Yp);
    fc_kernel<<<(BB * 10 + 255) / 256, 256>>>(fcW, fcb, out);
}

// round 7
// speedup vs baseline: 1.4789x; 1.2329x over previous
#include <cuda_runtime.h>
#include <cuda_bf16.h>

#define NN 100000
#define EE 1600000
#define BB 64
#define BNEPS 1e-5f
#define NBLK ((NN + 1023) / 1024)

// ---------------- scratch ----------------
__device__ __align__(16) float g_P[(size_t)NN * 4];            // layer-1 fp32 messages
__device__ __align__(16) __nv_bfloat16 g_Pb[(size_t)NN * 32];  // layer-2/3 bf16 messages
__device__ __align__(16) float g_A[(size_t)NN * 32];           // aggregation (fp32)
__device__ __align__(16) float g_Y[(size_t)NN * 64];           // final features
__device__ __align__(16) int g_degi[NN];
__device__ int g_rowptr[NN + 1];
__device__ int g_cursor[NN];
__device__ int g_src[EE];
__device__ int g_batch[NN];
__device__ float g_dis[NN];
__device__ float g_stats[128];      // scale[64], offset[64]
__device__ float g_M[1152];         // M1[din], then M2 padded rows (din+1)
__device__ int g_bsum[NBLK];
__device__ int g_boff[NBLK];
__device__ __align__(16) float g_pool[BB * 64];
__device__ float g_cnt[BB];

// local int64-vs-int32 detection for edge_index (first 64 entries as int64 all in [0,NN))
__device__ __forceinline__ int detect_e64(const void* ei) {
    const long long* p = (const long long*)ei;
    int ok = 1;
    for (int i = 0; i < 64; i++) {
        long long v = p[i];
        if (v < 0 || v >= NN) ok = 0;
    }
    return ok;
}

// ---------------- hist (degree) ----------------
__global__ void hist_kernel(const void* ei) {
    __shared__ int s64;
    if (threadIdx.x == 0) s64 = detect_e64(ei);
    __syncthreads();
    int e = blockIdx.x * blockDim.x + threadIdx.x;
    if (e >= EE) return;
    int c = s64 ? (int)((const long long*)ei)[EE + e] : ((const int*)ei)[EE + e];
    atomicAdd(&g_degi[c], 1);
}

// ---------------- scan phase 1 (+ batch decode) ----------------
__global__ void scan1_kernel(const void* batch) {
    __shared__ int s[256];
    __shared__ int s64b;
    int t = threadIdx.x;
    if (t == 0) {
        const long long* q = (const long long*)batch;
        int okb = 1;
        for (int i = 0; i < 32; i++) {
            long long v = q[NN / 4 + i];
            if (v < 0 || v >= BB) okb = 0;
        }
        s64b = okb;
    }
    int base = blockIdx.x * 1024 + t * 4;
    int sum = 0;
    if (base + 3 < NN) {
        int4 d = *(const int4*)&g_degi[base];
        sum = d.x + d.y + d.z + d.w;
    } else {
        for (int u = 0; u < 4; u++) if (base + u < NN) sum += g_degi[base + u];
    }
    s[t] = sum;
    __syncthreads();
    for (int off = 128; off > 0; off >>= 1) {
        if (t < off) s[t] += s[t + off];
        __syncthreads();
    }
    if (t == 0) g_bsum[blockIdx.x] = s[0];
    // batch decode (independent)
    int nt = gridDim.x * blockDim.x;
    int b64 = s64b;
    for (int i = blockIdx.x * blockDim.x + t; i < NN; i += nt)
        g_batch[i] = b64 ? (int)((const long long*)batch)[i] : ((const int*)batch)[i];
}

// ---------------- scan phase 2 (+ zero pool/cnt) ----------------
__global__ void scan2_kernel() {
    __shared__ int s[128];
    int t = threadIdx.x;
    int v = (t < NBLK) ? g_bsum[t] : 0;
    s[t] = v;
    __syncthreads();
    for (int off = 1; off < 128; off <<= 1) {
        int u = (t >= off) ? s[t - off] : 0;
        __syncthreads();
        s[t] += u;
        __syncthreads();
    }
    if (t < NBLK) g_boff[t] = s[t] - v;
    if (t == 127) g_rowptr[NN] = s[127];
    for (int u = t; u < BB * 64; u += 128) g_pool[u] = 0.0f;
    if (t < BB) g_cnt[t] = 0.0f;
}

// ---------------- scan phase 3 ----------------
__global__ void scan3_kernel() {
    __shared__ int s[256];
    int t = threadIdx.x;
    int base = blockIdx.x * 1024 + t * 4;
    int d0 = 0, d1 = 0, d2 = 0, d3 = 0;
    if (base + 3 < NN) {
        int4 d = *(const int4*)&g_degi[base];
        d0 = d.x; d1 = d.y; d2 = d.z; d3 = d.w;
    } else {
        if (base + 0 < NN) d0 = g_degi[base + 0];
        if (base + 1 < NN) d1 = g_degi[base + 1];
        if (base + 2 < NN) d2 = g_degi[base + 2];
        if (base + 3 < NN) d3 = g_degi[base + 3];
    }
    int tsum = d0 + d1 + d2 + d3;
    s[t] = tsum;
    __syncthreads();
    for (int off = 1; off < 256; off <<= 1) {
        int u = (t >= off) ? s[t - off] : 0;
        __syncthreads();
        s[t] += u;
        __syncthreads();
    }
    int off = g_boff[blockIdx.x] + s[t] - tsum;
    int pre[4] = {off, off + d0, off + d0 + d1, off + d0 + d1 + d2};
    int dd[4] = {d0, d1, d2, d3};
    for (int u = 0; u < 4; u++) {
        int idx = base + u;
        if (idx < NN) {
            g_rowptr[idx] = pre[u];
            g_cursor[idx] = pre[u];
            g_dis[idx] = rsqrtf((float)(dd[u] + 1));
        }
    }
}

// ---------------- fill CSR + prep layer-1 messages ----------------
__global__ void fillprep_kernel(const void* ei, const float* __restrict__ x) {
    __shared__ int s64;
    if (threadIdx.x == 0) s64 = detect_e64(ei);
    __syncthreads();
    int e = blockIdx.x * blockDim.x + threadIdx.x;
    if (e < EE) {
        int r, c;
        if (s64) {
            const long long* p = (const long long*)ei;
            r = (int)p[e]; c = (int)p[EE + e];
        } else {
            const int* p = (const int*)ei;
            r = p[e]; c = p[EE + e];
        }
        int pos = atomicAdd(&g_cursor[c], 1);
        g_src[pos] = r;
    }
    if (e < NN) {
        float d = g_dis[e];
        ((float4*)g_P)[e] = make_float4(x[3 * e] * d, x[3 * e + 1] * d, x[3 * e + 2] * d, 0.0f);
    }
}

// ---------------- layer-1 gather (fp32, 4 ch) + zero g_M ----------------
__global__ void gather1_kernel() {
    if (blockIdx.x == 0) {
        for (int u = threadIdx.x; u < 1152; u += blockDim.x) g_M[u] = 0.0f;
    }
    int i = blockIdx.x * blockDim.x + threadIdx.x;
    if (i >= NN) return;
    const float4* P4 = (const float4*)g_P;
    float4 acc = P4[i];
    int s = g_rowptr[i], e = g_rowptr[i + 1];
    for (int j = s; j < e; j++) {
        float4 v = P4[g_src[j]];
        acc.x += v.x; acc.y += v.y; acc.z += v.z; acc.w += v.w;
    }
    ((float4*)g_A)[i] = acc;
}

// ---------------- bf16 gather (CH channels, 8 per thread) + zero g_M ----------------
template <int CH>
__global__ void gather_bf16_kernel() {
    if (blockIdx.x == 0) {
        for (int u = threadIdx.x; u < 1152; u += blockDim.x) g_M[u] = 0.0f;
    }
    constexpr int TPN = CH / 8;   // threads per node
    int idx = blockIdx.x * blockDim.x + threadIdx.x;
    if (idx >= NN * TPN) return;
    int i = idx / TPN;
    int sub = idx % TPN;
    const uint4* Pb = (const uint4*)g_Pb;   // 16B = 8 bf16
    float acc[8];
    {
        uint4 v = Pb[(size_t)i * TPN + sub];
        const __nv_bfloat162* h = (const __nv_bfloat162*)&v;
#pragma unroll
        for (int u = 0; u < 4; u++) {
            float2 f = __bfloat1622float2(h[u]);
            acc[2 * u] = f.x; acc[2 * u + 1] = f.y;
        }
    }
    int s = g_rowptr[i], e = g_rowptr[i + 1];
    for (int j = s; j < e; j++) {
        uint4 v = Pb[(size_t)g_src[j] * TPN + sub];
        const __nv_bfloat162* h = (const __nv_bfloat162*)&v;
#pragma unroll
        for (int u = 0; u < 4; u++) {
            float2 f = __bfloat1622float2(h[u]);
            acc[2 * u] += f.x; acc[2 * u + 1] += f.y;
        }
    }
    float4* Ao = (float4*)(g_A + (size_t)i * CH + sub * 8);
    Ao[0] = make_float4(acc[0], acc[1], acc[2], acc[3]);
    Ao[1] = make_float4(acc[4], acc[5], acc[6], acc[7]);
}

// ---------------- moments din=3 (A astride 4) ----------------
__global__ void mom3_kernel() {
    __shared__ float Msh[12];
    int t = threadIdx.x;
    if (t < 12) Msh[t] = 0.0f;
    __syncthreads();
    float a1[3] = {0, 0, 0};
    float a2[9] = {0, 0, 0, 0, 0, 0, 0, 0, 0};
    int nt = gridDim.x * blockDim.x;
    for (int i = blockIdx.x * blockDim.x + t; i < NN; i += nt) {
        float4 v = ((const float4*)g_A)[i];
        float d = g_dis[i];
        float s0 = v.x * d, s1 = v.y * d, s2 = v.z * d;
        a1[0] += s0; a1[1] += s1; a1[2] += s2;
        a2[0] += s0 * s0; a2[1] += s0 * s1; a2[2] += s0 * s2;
        a2[3] += s1 * s0; a2[4] += s1 * s1; a2[5] += s1 * s2;
        a2[6] += s2 * s0; a2[7] += s2 * s1; a2[8] += s2 * s2;
    }
#pragma unroll
    for (int u = 0; u < 3; u++) {
        for (int o = 16; o > 0; o >>= 1) a1[u] += __shfl_down_sync(0xffffffffu, a1[u], o);
    }
#pragma unroll
    for (int u = 0; u < 9; u++) {
        for (int o = 16; o > 0; o >>= 1) a2[u] += __shfl_down_sync(0xffffffffu, a2[u], o);
    }
    if ((t & 31) == 0) {
        for (int u = 0; u < 3; u++) atomicAdd(&Msh[u], a1[u]);
        for (int u = 0; u < 9; u++) atomicAdd(&Msh[3 + u], a2[u]);
    }
    __syncthreads();
    if (t < 3) atomicAdd(&g_M[t], Msh[t]);
    if (t >= 3 && t < 12) {
        int u = t - 3;
        atomicAdd(&g_M[3 + (u / 3) * 4 + (u % 3)], Msh[t]);  // padded row stride din+1=4
    }
}

// ---------------- moments din=16/32 via warp shuffles ----------------
template <int DIN>
__global__ void mom_warp_kernel() {
    constexpr int RPW = 32 / DIN;
    constexpr int NIT = DIN + DIN * (DIN + 1);
    __shared__ float Msh[NIT];
    int t = threadIdx.x;
    for (int u = t; u < NIT; u += 256) Msh[u] = 0.0f;
    __syncthreads();
    int lane = t & 31, w = t >> 5;
    int gw = blockIdx.x * 8 + w;
    int sub = lane / DIN;
    int ch = lane % DIN;
    float acc1 = 0.0f;
    float acc2[DIN];
#pragma unroll
    for (int k = 0; k < DIN; k++) acc2[k] = 0.0f;
    int stride = gridDim.x * 8 * RPW;
    for (int r0 = gw * RPW; r0 < NN; r0 += stride) {
        int r = r0 + sub;   // NN divisible by RPW
        float s = g_A[(size_t)r * DIN + ch] * g_dis[r];
        acc1 += s;
#pragma unroll
        for (int k = 0; k < DIN; k++)
            acc2[k] += s * __shfl_sync(0xffffffffu, s, k, DIN);
    }
    atomicAdd(&Msh[ch], acc1);
#pragma unroll
    for (int k = 0; k < DIN; k++)
        atomicAdd(&Msh[DIN + ch * (DIN + 1) + k], acc2[k]);
    __syncthreads();
    for (int u = t; u < NIT; u += 256) atomicAdd(&g_M[u], Msh[u]);
}

// ---------------- solve BN affine from moments ----------------
__global__ void solve_kernel(const float* __restrict__ W, const float* __restrict__ bias,
                             const float* __restrict__ g, const float* __restrict__ be,
                             int din, int dout) {
    extern __shared__ float Wsh[];
    for (int u = threadIdx.x; u < din * dout; u += blockDim.x) Wsh[u] = W[u];
    __syncthreads();
    int c = threadIdx.x;
    if (c >= dout) return;
    float m1w = 0.0f;
    for (int k = 0; k < din; k++) m1w += g_M[k] * Wsh[k * dout + c];
    float q = 0.0f;
    for (int j = 0; j < din; j++) {
        float wj = Wsh[j * dout + c];
        const float* mrow = &g_M[din + j * (din + 1)];
        for (int k = 0; k < din; k++) q += wj * mrow[k] * Wsh[k * dout + c];
    }
    float bc = bias[c];
    const float inv_n = 1.0f / NN;
    float mu  = m1w * inv_n + bc;
    float ex2 = q * inv_n + 2.0f * bc * m1w * inv_n + bc * bc;
    float var = ex2 - mu * mu;
    float scale = g[c] * rsqrtf(var + BNEPS);
    float off = (bc - mu) * scale + be[c];
    g_stats[c] = scale;
    g_stats[64 + c] = off;
}

// ---------------- fused: h = relu(bn(dis*(A@W)+b)); write bf16 P or fp32 Y ----------------
__global__ void fused_out_kernel(const float* __restrict__ A, const float* __restrict__ W,
                                 int din, int astride, int dout, int ld, int to_bf16) {
    extern __shared__ float Wsh[];
    for (int u = threadIdx.x; u < astride * dout; u += blockDim.x)
        Wsh[u] = (u < din * dout) ? W[u] : 0.0f;
    __syncthreads();
    int t = threadIdx.x;
    int c = t & (dout - 1);
    float scale = g_stats[c];
    float off = g_stats[64 + c];
    int rpb = 256 >> ld;
    int rstart = blockIdx.x * rpb + (t >> ld);
    int rstride = gridDim.x * rpb;
    int nk4 = astride >> 2;
    for (int i = rstart; i < NN; i += rstride) {
        const float4* a4 = (const float4*)(A + (size_t)i * astride);
        float dot = 0.0f;
        for (int kk = 0; kk < nk4; kk++) {
            float4 av = a4[kk];
            int kb = kk * 4;
            dot += av.x * Wsh[(kb + 0) * dout + c];
            dot += av.y * Wsh[(kb + 1) * dout + c];
            dot += av.z * Wsh[(kb + 2) * dout + c];
            dot += av.w * Wsh[(kb + 3) * dout + c];
        }
        float d = g_dis[i];
        float h = fmaxf(d * dot * scale + off, 0.0f);
        if (to_bf16) g_Pb[(size_t)i * dout + c] = __float2bfloat16(h * d);
        else g_Y[(size_t)i * dout + c] = h;
    }
}

// ---------------- pooling + FC ----------------
__global__ void pool_kernel() {
    int idx = blockIdx.x * blockDim.x + threadIdx.x;
    if (idx >= NN * 16) return;
    int i = idx >> 4;
    int b = g_batch[i];
    float4 v = ((const float4*)g_Y)[idx];
    float* dst = g_pool + (size_t)b * 64 + (idx & 15) * 4;
    unsigned long long p = (unsigned long long)__cvta_generic_to_global(dst);
    asm volatile("red.global.add.v4.f32 [%0], {%1,%2,%3,%4};"
                 :: "l"(p), "f"(v.x), "f"(v.y), "f"(v.z), "f"(v.w) : "memory");
    if ((idx & 15) == 0) atomicAdd(&g_cnt[b], 1.0f);
}

__global__ void fc_kernel(const float* __restrict__ fcW, const float* __restrict__ fcb,
                          float* __restrict__ out) {
    int t = blockIdx.x * blockDim.x + threadIdx.x;
    if (t >= BB * 10) return;
    int b = t / 10;
    int k = t % 10;
    float cnt = fmaxf(g_cnt[b], 1.0f);
    float s = 0.0f;
    for (int j = 0; j < 64; j++) s += g_pool[b * 64 + j] * fcW[j * 10 + k];
    out[t] = s / cnt + fcb[k];
}

extern "C" void kernel_launch(void* const* d_in, const int* in_sizes, int n_in,
                              void* d_out, int out_size) {
    const float* x     = (const float*)d_in[0];
    const void*  ei    = d_in[1];
    const void*  batch = d_in[2];
    const float* W1 = (const float*)d_in[3];
    const float* b1 = (const float*)d_in[4];
    const float* g1 = (const float*)d_in[5];
    const float* be1 = (const float*)d_in[6];
    const float* W2 = (const float*)d_in[7];
    const float* b2 = (const float*)d_in[8];
    const float* g2 = (const float*)d_in[9];
    const float* be2 = (const float*)d_in[10];
    const float* W3 = (const float*)d_in[11];
    const float* b3 = (const float*)d_in[12];
    const float* g3 = (const float*)d_in[13];
    const float* be3 = (const float*)d_in[14];
    const float* fcW = (const float*)d_in[15];
    const float* fcb = (const float*)d_in[16];
    float* out = (float*)d_out;

    float* Ap;
    int* degp;
    cudaGetSymbolAddress((void**)&Ap, g_A);
    cudaGetSymbolAddress((void**)&degp, g_degi);

    // ---- CSR build ----
    cudaMemsetAsync(degp, 0, NN * sizeof(int));
    hist_kernel<<<(EE + 255) / 256, 256>>>(ei);
    scan1_kernel<<<NBLK, 256>>>(batch);
    scan2_kernel<<<1, 128>>>();
    scan3_kernel<<<NBLK, 256>>>();
    fillprep_kernel<<<(EE + 255) / 256, 256>>>(ei, x);

    // ---- layer 1 (3->16) ----
    gather1_kernel<<<(NN + 255) / 256, 256>>>();
    mom3_kernel<<<128, 256>>>();
    solve_kernel<<<1, 64, 3 * 16 * sizeof(float)>>>(W1, b1, g1, be1, 3, 16);
    fused_out_kernel<<<1024, 256, 4 * 16 * sizeof(float)>>>(Ap, W1, 3, 4, 16, 4, 1);

    // ---- layer 2 (16->32) ----
    gather_bf16_kernel<16><<<(NN * 2 + 255) / 256, 256>>>();
    mom_warp_kernel<16><<<128, 256>>>();
    solve_kernel<<<1, 64, 16 * 32 * sizeof(float)>>>(W2, b2, g2, be2, 16, 32);
    fused_out_kernel<<<1024, 256, 16 * 32 * sizeof(float)>>>(Ap, W2, 16, 16, 32, 5, 1);

    // ---- layer 3 (32->64) ----
    gather_bf16_kernel<32><<<(NN * 4 + 255) / 256, 256>>>();
    mom_warp_kernel<32><<<128, 256>>>();
    solve_kernel<<<1, 64, 32 * 64 * sizeof(float)>>>(W3, b3, g3, be3, 32, 64);
    fused_out_kernel<<<1024, 256, 32 * 64 * sizeof(float)>>>(Ap, W3, 32, 32, 64, 6, 0);

    // ---- pooling + FC ----
    pool_kernel<<<(NN * 16 + 255) / 256, 256>>>();
    fc_kernel<<<(BB * 10 + 255) / 256, 256>>>(fcW, fcb, out);
}